// round 8
// baseline (speedup 1.0000x reference)
#include <cuda_runtime.h>
#include <cuda_bf16.h>
#include <cstdint>
#include <cstddef>

#define NSLAB 2048
// ---------------- SMEM layout (bytes) ----------------
#define W_OFF  0                    // W bf16 [256][512B] swizzled = 131072
#define XB_OFF 131072               // 2 x 32768 x-slab bf16 swizzled
#define Y_OFF  196608               // y bf16 [64][512B] swizzled = 32768 (partials overlay)
#define SMEM_BYTES 229376

__device__ __nv_bfloat16 g_Wbf[256 * 256];

// ---------------- helpers ----------------
__device__ __forceinline__ uint32_t smem_u32(const void* p) {
    uint32_t a;
    asm("{ .reg .u64 t; cvta.to.shared.u64 t, %1; cvt.u32.u64 %0, t; }" : "=r"(a) : "l"(p));
    return a;
}
__device__ __forceinline__ void cp_async16(uint32_t dst, const void* src) {
    asm volatile("cp.async.cg.shared.global [%0], [%1], 16;" :: "r"(dst), "l"(src));
}
__device__ __forceinline__ void cp_commit() { asm volatile("cp.async.commit_group;"); }
template <int N>
__device__ __forceinline__ void cp_wait() { asm volatile("cp.async.wait_group %0;" :: "n"(N) : "memory"); }

__device__ __forceinline__ void ldsm4(uint32_t& r0, uint32_t& r1, uint32_t& r2, uint32_t& r3, uint32_t a) {
    asm volatile("ldmatrix.sync.aligned.m8n8.x4.shared.b16 {%0,%1,%2,%3}, [%4];"
                 : "=r"(r0), "=r"(r1), "=r"(r2), "=r"(r3) : "r"(a));
}
__device__ __forceinline__ void mma_bf16(float& d0, float& d1, float& d2, float& d3,
                                         uint32_t a0, uint32_t a1, uint32_t a2, uint32_t a3,
                                         uint32_t b0, uint32_t b1) {
    asm volatile("mma.sync.aligned.m16n8k16.row.col.f32.bf16.bf16.f32 "
                 "{%0,%1,%2,%3}, {%4,%5,%6,%7}, {%8,%9}, {%0,%1,%2,%3};"
                 : "+f"(d0), "+f"(d1), "+f"(d2), "+f"(d3)
                 : "r"(a0), "r"(a1), "r"(a2), "r"(a3), "r"(b0), "r"(b1));
}
__device__ __forceinline__ void sts128(uint32_t a, uint32_t r0, uint32_t r1, uint32_t r2, uint32_t r3) {
    asm volatile("st.shared.v4.b32 [%0], {%1,%2,%3,%4};" :: "r"(a), "r"(r0), "r"(r1), "r"(r2), "r"(r3));
}
__device__ __forceinline__ void sts32(uint32_t a, uint32_t v) {
    asm volatile("st.shared.b32 [%0], %1;" :: "r"(a), "r"(v));
}
__device__ __forceinline__ void sts64f(uint32_t a, float v0, float v1) {
    asm volatile("st.shared.v2.f32 [%0], {%1,%2};" :: "r"(a), "f"(v0), "f"(v1));
}
__device__ __forceinline__ uint32_t lds_u32(uint32_t a) {
    uint32_t v; asm volatile("ld.shared.b32 %0, [%1];" : "=r"(v) : "r"(a)); return v;
}
__device__ __forceinline__ float tanh_f(float v) {
    float r; asm("tanh.approx.f32 %0, %1;" : "=f"(r) : "f"(v)); return r;
}
__device__ __forceinline__ uint32_t packbf(float a, float b) {
    __nv_bfloat162 v = __floats2bfloat162_rn(a, b);
    return *reinterpret_cast<uint32_t*>(&v);
}
__device__ __forceinline__ void bar_sync(int id, int cnt) {
    asm volatile("bar.sync %0, %1;" :: "r"(id), "r"(cnt) : "memory");
}
__device__ __forceinline__ void bar_arrive(int id, int cnt) {
    asm volatile("bar.arrive %0, %1;" :: "r"(id), "r"(cnt) : "memory");
}
__device__ __forceinline__ void membar_cta() {
    asm volatile("membar.cta;" ::: "memory");
}

// ---------------- W pre-conversion ----------------
__global__ void conv_w(const float* __restrict__ W) {
    int i = blockIdx.x * 256 + threadIdx.x;
    float4 v = reinterpret_cast<const float4*>(W)[i];
    uint32_t* dst = reinterpret_cast<uint32_t*>(g_Wbf);
    dst[i * 2]     = packbf(v.x, v.y);
    dst[i * 2 + 1] = packbf(v.z, v.w);
}

// ---------------- warp-specialized persistent kernel ----------------
__global__ __launch_bounds__(512, 1)
void attend_ws(const float* __restrict__ x, const float* __restrict__ b,
               const float* __restrict__ ctx, float* __restrict__ out)
{
    extern __shared__ char sm[];
    const uint32_t sb = smem_u32(sm);
    float* smf = reinterpret_cast<float*>(sm);
    const int tid = threadIdx.x;
    const int lane = tid & 31, wid = tid >> 5;
    const int grid = gridDim.x, bid = blockIdx.x;
    const int nit = (NSLAB - 1 - bid) / grid + 1;

    // ---- prologue: W resident + xb[0], xb[1] ----
    {
        const char* wsrc = reinterpret_cast<const char*>(g_Wbf);
        #pragma unroll
        for (int i = 0; i < 16; ++i) {
            int cid = tid + i * 512;
            int o = cid >> 5, ch = cid & 31;
            cp_async16(sb + W_OFF + (uint32_t)(o * 512 + ((ch ^ (o & 7)) << 4)),
                       wsrc + (size_t)o * 512 + ch * 16);
        }
        cp_commit();
        #pragma unroll
        for (int buf = 0; buf < 2; ++buf) {
            int sl = bid + buf * grid; if (sl >= NSLAB) sl = bid;
            const float4* xg = reinterpret_cast<const float4*>(x + (size_t)sl * 16384);
            #pragma unroll
            for (int i = 0; i < 4; ++i) {
                int cid = tid + i * 512;
                int w = cid >> 5, cc = cid & 31;
                float4 v0 = __ldg(xg + cid * 2), v1 = __ldg(xg + cid * 2 + 1);
                sts128(sb + XB_OFF + (uint32_t)(buf * 32768 + w * 512 + ((cc ^ (w & 7)) << 4)),
                       packbf(v0.x, v0.y), packbf(v0.z, v0.w),
                       packbf(v1.x, v1.y), packbf(v1.z, v1.w));
            }
        }
        cp_wait<0>();
    }
    __syncthreads();

    if (wid < 8) {
        // ================= MMA warps: m64 x n32 each =================
        const int wn = wid;
        const int l7 = lane & 7;
        const int arow_off = l7 + ((lane >> 3) & 1) * 8;
        const int acb  = lane >> 4;
        const int brow = l7 + (lane >> 4) * 8;
        const int bch  = (lane >> 3) & 1;
        const int q = lane >> 2, r = lane & 3;

        for (int it = 0; it < nit; ++it) {
            const uint32_t xbb = sb + XB_OFF + (uint32_t)((it & 1) * 32768);
            float c[4][4][4];
            #pragma unroll
            for (int mt = 0; mt < 4; ++mt)
                #pragma unroll
                for (int nt = 0; nt < 4; ++nt)
                    #pragma unroll
                    for (int e = 0; e < 4; ++e) c[mt][nt][e] = 0.f;

            #pragma unroll
            for (int ks = 0; ks < 16; ++ks) {
                uint32_t a[4][4];
                #pragma unroll
                for (int mt = 0; mt < 4; ++mt) {
                    int row = mt * 16 + arow_off;
                    int cb = ks * 2 + acb;
                    ldsm4(a[mt][0], a[mt][1], a[mt][2], a[mt][3],
                          xbb + (uint32_t)(row * 512 + ((cb ^ (row & 7)) << 4)));
                }
                uint32_t bf2[4][2];
                #pragma unroll
                for (int pp = 0; pp < 2; ++pp) {
                    int rowb = wn * 32 + pp * 16 + brow;
                    int ch = ks * 2 + bch;
                    ldsm4(bf2[2*pp][0], bf2[2*pp][1], bf2[2*pp+1][0], bf2[2*pp+1][1],
                          sb + W_OFF + (uint32_t)(rowb * 512 + ((ch ^ (rowb & 7)) << 4)));
                }
                #pragma unroll
                for (int mt = 0; mt < 4; ++mt)
                    #pragma unroll
                    for (int nt = 0; nt < 4; ++nt)
                        mma_bf16(c[mt][nt][0], c[mt][nt][1], c[mt][nt][2], c[mt][nt][3],
                                 a[mt][0], a[mt][1], a[mt][2], a[mt][3],
                                 bf2[nt][0], bf2[nt][1]);
            }

            bar_sync(2, 512);        // ybuf free + xb(it+2 buffer) refilled
            #pragma unroll
            for (int mt = 0; mt < 4; ++mt) {
                #pragma unroll
                for (int nt = 0; nt < 4; ++nt) {
                    int ch = wn * 4 + nt;
                    int r0 = mt * 16 + q, r1 = r0 + 8;
                    sts32(sb + Y_OFF + (uint32_t)(r0 * 512 + ((ch ^ (r0 & 7)) << 4) + 4 * r),
                          packbf(c[mt][nt][0], c[mt][nt][1]));
                    sts32(sb + Y_OFF + (uint32_t)(r1 * 512 + ((ch ^ (r1 & 7)) << 4) + 4 * r),
                          packbf(c[mt][nt][2], c[mt][nt][3]));
                }
            }
            membar_cta();
            bar_arrive(1, 512);      // y ready
        }
    } else {
        // ================= EPI warps =================
        const int ewid = wid - 8;            // rows ewid*8 .. ewid*8+7
        const int l = lane;
        const int et = tid - 256;            // 0..255
        float2 bfr[4], cfr[4];
        #pragma unroll
        for (int j = 0; j < 4; ++j) {
            bfr[j] = __ldg(reinterpret_cast<const float2*>(b + 2 * l + 64 * j));
            cfr[j] = __ldg(reinterpret_cast<const float2*>(ctx + 2 * l + 64 * j));
        }
        bar_arrive(2, 512);                  // initial: ybuf free

        for (int it = 0; it < nit; ++it) {
            const int s = bid + it * grid;
            const float* xs = x + (size_t)s * 16384;

            // ---- pre-wait prefetch (independent of y) ----
            float2 xq0[4][4];                           // x rows 0-3 for alpha
            #pragma unroll
            for (int i = 0; i < 4; ++i) {
                int row = ewid * 8 + i;
                #pragma unroll
                for (int j = 0; j < 4; ++j)
                    xq0[i][j] = __ldg(reinterpret_cast<const float2*>(
                                      xs + row * 256 + 2 * l + 64 * j));
            }
            const int s2 = s + 2 * grid;
            const bool do2 = (s2 < NSLAB);
            const float4* xg2 = reinterpret_cast<const float4*>(
                x + (size_t)(do2 ? s2 : s) * 16384);
            float4 xb1[8];                              // xb refill half 1
            if (do2) {
                #pragma unroll
                for (int i = 0; i < 4; ++i) {
                    int cid = et + i * 256;
                    xb1[2*i]   = __ldg(xg2 + cid * 2);
                    xb1[2*i+1] = __ldg(xg2 + cid * 2 + 1);
                }
            }

            bar_sync(1, 512);                // y(s) ready
            const uint32_t xbdst = sb + XB_OFF + (uint32_t)((it & 1) * 32768);

            // drain prefetches off the critical path first
            if (do2) {
                #pragma unroll
                for (int i = 0; i < 4; ++i) {
                    int cid = et + i * 256;
                    int w = cid >> 5, cc = cid & 31;
                    sts128(xbdst + (uint32_t)(w * 512 + ((cc ^ (w & 7)) << 4)),
                           packbf(xb1[2*i].x, xb1[2*i].y), packbf(xb1[2*i].z, xb1[2*i].w),
                           packbf(xb1[2*i+1].x, xb1[2*i+1].y), packbf(xb1[2*i+1].z, xb1[2*i+1].w));
                }
            }
            float4 xb2[8];                              // xb refill half 2
            if (do2) {
                #pragma unroll
                for (int i = 0; i < 4; ++i) {
                    int cid = et + (i + 4) * 256;
                    xb2[2*i]   = __ldg(xg2 + cid * 2);
                    xb2[2*i+1] = __ldg(xg2 + cid * 2 + 1);
                }
            }
            float2 xq1[4][4];                           // x rows 4-7 for alpha
            #pragma unroll
            for (int i = 0; i < 4; ++i) {
                int row = ewid * 8 + 4 + i;
                #pragma unroll
                for (int j = 0; j < 4; ++j)
                    xq1[i][j] = __ldg(reinterpret_cast<const float2*>(
                                      xs + row * 256 + 2 * l + 64 * j));
            }

            float p[8];
            #pragma unroll
            for (int k = 0; k < 8; ++k) p[k] = 0.f;

            // ---- process rows (critical path: LDS y -> tanh -> rowsum -> acc) ----
            #pragma unroll
            for (int rg = 0; rg < 2; ++rg) {
                float ee[4][8], iv[4];
                #pragma unroll
                for (int i = 0; i < 4; ++i) {
                    int row = ewid * 8 + rg * 4 + i;
                    uint32_t rb = sb + Y_OFF + (uint32_t)(row * 512);
                    float rsum = 0.f;
                    #pragma unroll
                    for (int j = 0; j < 4; ++j) {
                        int ch = (l >> 2) + 8 * j;
                        uint32_t u = lds_u32(rb + (uint32_t)(((ch ^ (row & 7)) << 4) + (l & 3) * 4));
                        float y0 = __uint_as_float(u << 16);
                        float y1 = __uint_as_float(u & 0xFFFF0000u);
                        float t0 = tanh_f(y0 + bfr[j].x) * cfr[j].x;
                        float t1 = tanh_f(y1 + bfr[j].y) * cfr[j].y;
                        float e0 = fmaf(t0, fmaf(t0, fmaf(t0, 0.16666667f, 0.5f), 1.f), 1.f);
                        float e1 = fmaf(t1, fmaf(t1, fmaf(t1, 0.16666667f, 0.5f), 1.f), 1.f);
                        ee[i][2*j] = e0; ee[i][2*j+1] = e1;
                        rsum += e0 + e1;
                    }
                    #pragma unroll
                    for (int off = 16; off; off >>= 1)
                        rsum += __shfl_xor_sync(0xFFFFFFFFu, rsum, off);
                    iv[i] = __fdividef(1.f, rsum);
                }
                #pragma unroll
                for (int i = 0; i < 4; ++i) {
                    #pragma unroll
                    for (int j = 0; j < 4; ++j) {
                        float2 xv = rg ? xq1[i][j] : xq0[i][j];
                        p[2*j]   = fmaf(ee[i][2*j]   * iv[i], xv.x, p[2*j]);
                        p[2*j+1] = fmaf(ee[i][2*j+1] * iv[i], xv.y, p[2*j+1]);
                    }
                }
            }

            // xb refill half 2 (off critical path; gated only by arrive(2))
            if (do2) {
                #pragma unroll
                for (int i = 0; i < 4; ++i) {
                    int cid = et + (i + 4) * 256;
                    int w = cid >> 5, cc = cid & 31;
                    sts128(xbdst + (uint32_t)(w * 512 + ((cc ^ (w & 7)) << 4)),
                           packbf(xb2[2*i].x, xb2[2*i].y), packbf(xb2[2*i].z, xb2[2*i].w),
                           packbf(xb2[2*i+1].x, xb2[2*i+1].y), packbf(xb2[2*i+1].z, xb2[2*i+1].w));
                }
            }

            bar_sync(3, 256);                // epi warps done reading ybuf
            #pragma unroll
            for (int j = 0; j < 4; ++j)
                sts64f(sb + Y_OFF + (uint32_t)(ewid * 1024 + (2 * l + 64 * j) * 4),
                       p[2*j], p[2*j+1]);
            bar_sync(3, 256);                // partials visible
            {
                float o = 0.f;
                #pragma unroll
                for (int we = 0; we < 8; ++we)
                    o += smf[Y_OFF / 4 + we * 256 + et];
                out[(size_t)s * 256 + et] = o;
            }
            membar_cta();
            bar_arrive(2, 512);              // ybuf free + xb refilled
        }
    }
}

extern "C" void kernel_launch(void* const* d_in, const int* in_sizes, int n_in,
                              void* d_out, int out_size)
{
    const float* x   = (const float*)d_in[0];
    const float* Wm  = (const float*)d_in[1];
    const float* b   = (const float*)d_in[2];
    const float* ctx = (const float*)d_in[3];
    float* out = (float*)d_out;

    int dev = 0, sms = 148;
    cudaGetDevice(&dev);
    cudaDeviceGetAttribute(&sms, cudaDevAttrMultiProcessorCount, dev);

    cudaFuncSetAttribute(attend_ws, cudaFuncAttributeMaxDynamicSharedMemorySize, SMEM_BYTES);

    conv_w<<<64, 256>>>(Wm);
    attend_ws<<<sms, 512, SMEM_BYTES>>>(x, b, ctx, out);
}

// round 10
// speedup vs baseline: 1.2373x; 1.2373x over previous
#include <cuda_runtime.h>
#include <cuda_bf16.h>
#include <cstdint>
#include <cstddef>

#define NSLAB 2048
// ---------------- SMEM layout (bytes) ----------------
#define W_OFF  0                    // W bf16 [256][512B] swizzled = 131072
#define XB_OFF 131072               // 2 x 32768 x-slab bf16 swizzled
#define Y_OFF  196608               // y bf16 [64][512B] swizzled = 32768 (partials overlay)
#define BC_OFF 229376               // f32 b[256], ctx[256] = 2048
#define SMEM_BYTES 231424

__device__ __nv_bfloat16 g_Wbf[256 * 256];

// ---------------- helpers ----------------
__device__ __forceinline__ uint32_t smem_u32(const void* p) {
    uint32_t a;
    asm("{ .reg .u64 t; cvta.to.shared.u64 t, %1; cvt.u32.u64 %0, t; }" : "=r"(a) : "l"(p));
    return a;
}
__device__ __forceinline__ void cp_async16(uint32_t dst, const void* src) {
    asm volatile("cp.async.cg.shared.global [%0], [%1], 16;" :: "r"(dst), "l"(src));
}
__device__ __forceinline__ void cp_commit() { asm volatile("cp.async.commit_group;"); }
template <int N>
__device__ __forceinline__ void cp_wait() { asm volatile("cp.async.wait_group %0;" :: "n"(N) : "memory"); }

__device__ __forceinline__ void ldsm4(uint32_t& r0, uint32_t& r1, uint32_t& r2, uint32_t& r3, uint32_t a) {
    asm volatile("ldmatrix.sync.aligned.m8n8.x4.shared.b16 {%0,%1,%2,%3}, [%4];"
                 : "=r"(r0), "=r"(r1), "=r"(r2), "=r"(r3) : "r"(a));
}
__device__ __forceinline__ void mma_bf16(float& d0, float& d1, float& d2, float& d3,
                                         uint32_t a0, uint32_t a1, uint32_t a2, uint32_t a3,
                                         uint32_t b0, uint32_t b1) {
    asm volatile("mma.sync.aligned.m16n8k16.row.col.f32.bf16.bf16.f32 "
                 "{%0,%1,%2,%3}, {%4,%5,%6,%7}, {%8,%9}, {%0,%1,%2,%3};"
                 : "+f"(d0), "+f"(d1), "+f"(d2), "+f"(d3)
                 : "r"(a0), "r"(a1), "r"(a2), "r"(a3), "r"(b0), "r"(b1));
}
__device__ __forceinline__ void sts128(uint32_t a, uint32_t r0, uint32_t r1, uint32_t r2, uint32_t r3) {
    asm volatile("st.shared.v4.b32 [%0], {%1,%2,%3,%4};" :: "r"(a), "r"(r0), "r"(r1), "r"(r2), "r"(r3));
}
__device__ __forceinline__ void sts32(uint32_t a, uint32_t v) {
    asm volatile("st.shared.b32 [%0], %1;" :: "r"(a), "r"(v));
}
__device__ __forceinline__ void sts64f(uint32_t a, float v0, float v1) {
    asm volatile("st.shared.v2.f32 [%0], {%1,%2};" :: "r"(a), "f"(v0), "f"(v1));
}
__device__ __forceinline__ uint32_t lds_u32(uint32_t a) {
    uint32_t v; asm volatile("ld.shared.b32 %0, [%1];" : "=r"(v) : "r"(a)); return v;
}
__device__ __forceinline__ float2 lds_f2(uint32_t a) {
    float2 v;
    asm volatile("ld.shared.v2.f32 {%0,%1}, [%2];" : "=f"(v.x), "=f"(v.y) : "r"(a));
    return v;
}
__device__ __forceinline__ float tanh_f(float v) {
    float r; asm("tanh.approx.f32 %0, %1;" : "=f"(r) : "f"(v)); return r;
}
__device__ __forceinline__ uint32_t packbf(float a, float b) {
    __nv_bfloat162 v = __floats2bfloat162_rn(a, b);
    return *reinterpret_cast<uint32_t*>(&v);
}
__device__ __forceinline__ void bar_sync(int id, int cnt) {
    asm volatile("bar.sync %0, %1;" :: "r"(id), "r"(cnt) : "memory");
}
__device__ __forceinline__ void bar_arrive(int id, int cnt) {
    asm volatile("bar.arrive %0, %1;" :: "r"(id), "r"(cnt) : "memory");
}
__device__ __forceinline__ void membar_cta() {
    asm volatile("membar.cta;" ::: "memory");
}

// ---------------- W pre-conversion ----------------
__global__ void conv_w(const float* __restrict__ W) {
    int i = blockIdx.x * 256 + threadIdx.x;
    float4 v = reinterpret_cast<const float4*>(W)[i];
    uint32_t* dst = reinterpret_cast<uint32_t*>(g_Wbf);
    dst[i * 2]     = packbf(v.x, v.y);
    dst[i * 2 + 1] = packbf(v.z, v.w);
}

// ---------------- warp-specialized persistent kernel ----------------
__global__ __launch_bounds__(512, 1)
void attend_ws(const float* __restrict__ x, const float* __restrict__ b,
               const float* __restrict__ ctx, float* __restrict__ out)
{
    extern __shared__ char sm[];
    const uint32_t sb = smem_u32(sm);
    float* smf = reinterpret_cast<float*>(sm);
    const int tid = threadIdx.x;
    const int lane = tid & 31, wid = tid >> 5;
    const int grid = gridDim.x, bid = blockIdx.x;
    const int nit = (NSLAB - 1 - bid) / grid + 1;

    // ---- prologue: W resident + xb[0], xb[1] + bc ----
    {
        const char* wsrc = reinterpret_cast<const char*>(g_Wbf);
        #pragma unroll
        for (int i = 0; i < 16; ++i) {
            int cid = tid + i * 512;
            int o = cid >> 5, ch = cid & 31;
            cp_async16(sb + W_OFF + (uint32_t)(o * 512 + ((ch ^ (o & 7)) << 4)),
                       wsrc + (size_t)o * 512 + ch * 16);
        }
        cp_commit();
        #pragma unroll
        for (int buf = 0; buf < 2; ++buf) {
            int sl = bid + buf * grid; if (sl >= NSLAB) sl = bid;
            const float4* xg = reinterpret_cast<const float4*>(x + (size_t)sl * 16384);
            #pragma unroll
            for (int i = 0; i < 4; ++i) {
                int cid = tid + i * 512;
                int w = cid >> 5, cc = cid & 31;
                float4 v0 = __ldg(xg + cid * 2), v1 = __ldg(xg + cid * 2 + 1);
                sts128(sb + XB_OFF + (uint32_t)(buf * 32768 + w * 512 + ((cc ^ (w & 7)) << 4)),
                       packbf(v0.x, v0.y), packbf(v0.z, v0.w),
                       packbf(v1.x, v1.y), packbf(v1.z, v1.w));
            }
        }
        if (tid < 256) {
            smf[BC_OFF / 4 + tid]       = __ldg(b + tid);
            smf[BC_OFF / 4 + 256 + tid] = __ldg(ctx + tid);
        }
        cp_wait<0>();
    }
    __syncthreads();

    if (wid < 8) {
        // ================= MMA warps: m64 x n32 each =================
        const int wn = wid;
        const int l7 = lane & 7;
        const int arow_off = l7 + ((lane >> 3) & 1) * 8;
        const int acb  = lane >> 4;
        const int brow = l7 + (lane >> 4) * 8;
        const int bch  = (lane >> 3) & 1;
        const int q = lane >> 2, r = lane & 3;

        for (int it = 0; it < nit; ++it) {
            const uint32_t xbb = sb + XB_OFF + (uint32_t)((it & 1) * 32768);
            float c[4][4][4];
            #pragma unroll
            for (int mt = 0; mt < 4; ++mt)
                #pragma unroll
                for (int nt = 0; nt < 4; ++nt)
                    #pragma unroll
                    for (int e = 0; e < 4; ++e) c[mt][nt][e] = 0.f;

            #pragma unroll
            for (int ks = 0; ks < 16; ++ks) {
                uint32_t a[4][4];
                #pragma unroll
                for (int mt = 0; mt < 4; ++mt) {
                    int row = mt * 16 + arow_off;
                    int cb = ks * 2 + acb;
                    ldsm4(a[mt][0], a[mt][1], a[mt][2], a[mt][3],
                          xbb + (uint32_t)(row * 512 + ((cb ^ (row & 7)) << 4)));
                }
                uint32_t bf2[4][2];
                #pragma unroll
                for (int pp = 0; pp < 2; ++pp) {
                    int rowb = wn * 32 + pp * 16 + brow;
                    int ch = ks * 2 + bch;
                    ldsm4(bf2[2*pp][0], bf2[2*pp][1], bf2[2*pp+1][0], bf2[2*pp+1][1],
                          sb + W_OFF + (uint32_t)(rowb * 512 + ((ch ^ (rowb & 7)) << 4)));
                }
                #pragma unroll
                for (int mt = 0; mt < 4; ++mt)
                    #pragma unroll
                    for (int nt = 0; nt < 4; ++nt)
                        mma_bf16(c[mt][nt][0], c[mt][nt][1], c[mt][nt][2], c[mt][nt][3],
                                 a[mt][0], a[mt][1], a[mt][2], a[mt][3],
                                 bf2[nt][0], bf2[nt][1]);
            }

            bar_sync(2, 512);        // ybuf free + xb(it+2 buffer) refilled
            #pragma unroll
            for (int mt = 0; mt < 4; ++mt) {
                #pragma unroll
                for (int nt = 0; nt < 4; ++nt) {
                    int ch = wn * 4 + nt;
                    int r0 = mt * 16 + q, r1 = r0 + 8;
                    sts32(sb + Y_OFF + (uint32_t)(r0 * 512 + ((ch ^ (r0 & 7)) << 4) + 4 * r),
                          packbf(c[mt][nt][0], c[mt][nt][1]));
                    sts32(sb + Y_OFF + (uint32_t)(r1 * 512 + ((ch ^ (r1 & 7)) << 4) + 4 * r),
                          packbf(c[mt][nt][2], c[mt][nt][3]));
                }
            }
            membar_cta();
            bar_arrive(1, 512);      // y ready
        }
    } else {
        // ================= EPI warps =================
        const int ewid = wid - 8;            // rows ewid*8 .. ewid*8+7
        const int l = lane;
        const int et = tid - 256;            // 0..255
        const uint32_t bcb = sb + BC_OFF;
        bar_arrive(2, 512);                  // initial: ybuf free

        for (int it = 0; it < nit; ++it) {
            const int s = bid + it * grid;
            const float* xs = x + (size_t)s * 16384;

            bar_sync(1, 512);                // y(s) ready

            const int s2 = s + 2 * grid;
            const bool do2 = (s2 < NSLAB);
            const float4* xg2 = reinterpret_cast<const float4*>(
                x + (size_t)(do2 ? s2 : s) * 16384);
            const uint32_t xbdst = sb + XB_OFF + (uint32_t)((it & 1) * 32768);

            // refill batch 1 LDG (latency hidden under rg0 y processing)
            float4 xb1[8];
            if (do2) {
                #pragma unroll
                for (int i = 0; i < 4; ++i) {
                    int cid = et + i * 256;
                    xb1[2*i]   = __ldg(xg2 + cid * 2);
                    xb1[2*i+1] = __ldg(xg2 + cid * 2 + 1);
                }
            }

            float p[8];
            #pragma unroll
            for (int k = 0; k < 8; ++k) p[k] = 0.f;

            #pragma unroll
            for (int rg = 0; rg < 2; ++rg) {
                // per-rg alpha-x loads (hidden under tanh/LDS below)
                float2 xq[4][4];
                #pragma unroll
                for (int i = 0; i < 4; ++i) {
                    int row = ewid * 8 + rg * 4 + i;
                    #pragma unroll
                    for (int j = 0; j < 4; ++j)
                        xq[i][j] = __ldg(reinterpret_cast<const float2*>(
                                         xs + row * 256 + 2 * l + 64 * j));
                }
                float ee[4][8], iv[4];
                #pragma unroll
                for (int i = 0; i < 4; ++i) {
                    int row = ewid * 8 + rg * 4 + i;
                    uint32_t rb = sb + Y_OFF + (uint32_t)(row * 512);
                    float rsum = 0.f;
                    #pragma unroll
                    for (int j = 0; j < 4; ++j) {
                        int ch = (l >> 2) + 8 * j;
                        uint32_t u = lds_u32(rb + (uint32_t)(((ch ^ (row & 7)) << 4) + (l & 3) * 4));
                        float2 bo = lds_f2(bcb + (uint32_t)((2 * l + 64 * j) * 4));
                        float2 co = lds_f2(bcb + (uint32_t)((2 * l + 64 * j + 256) * 4));
                        float y0 = __uint_as_float(u << 16);
                        float y1 = __uint_as_float(u & 0xFFFF0000u);
                        float t0 = tanh_f(y0 + bo.x) * co.x;
                        float t1 = tanh_f(y1 + bo.y) * co.y;
                        float e0 = fmaf(t0, fmaf(t0, fmaf(t0, 0.16666667f, 0.5f), 1.f), 1.f);
                        float e1 = fmaf(t1, fmaf(t1, fmaf(t1, 0.16666667f, 0.5f), 1.f), 1.f);
                        ee[i][2*j] = e0; ee[i][2*j+1] = e1;
                        rsum += e0 + e1;
                    }
                    #pragma unroll
                    for (int off = 16; off; off >>= 1)
                        rsum += __shfl_xor_sync(0xFFFFFFFFu, rsum, off);
                    iv[i] = __fdividef(1.f, rsum);
                }
                #pragma unroll
                for (int i = 0; i < 4; ++i) {
                    #pragma unroll
                    for (int j = 0; j < 4; ++j) {
                        p[2*j]   = fmaf(ee[i][2*j]   * iv[i], xq[i][j].x, p[2*j]);
                        p[2*j+1] = fmaf(ee[i][2*j+1] * iv[i], xq[i][j].y, p[2*j+1]);
                    }
                }

                if (rg == 0 && do2) {
                    // store refill batch 1; issue batch 2 LDG (hidden under rg1)
                    #pragma unroll
                    for (int i = 0; i < 4; ++i) {
                        int cid = et + i * 256;
                        int w = cid >> 5, cc = cid & 31;
                        sts128(xbdst + (uint32_t)(w * 512 + ((cc ^ (w & 7)) << 4)),
                               packbf(xb1[2*i].x, xb1[2*i].y), packbf(xb1[2*i].z, xb1[2*i].w),
                               packbf(xb1[2*i+1].x, xb1[2*i+1].y), packbf(xb1[2*i+1].z, xb1[2*i+1].w));
                    }
                    #pragma unroll
                    for (int i = 0; i < 4; ++i) {
                        int cid = et + (i + 4) * 256;
                        xb1[2*i]   = __ldg(xg2 + cid * 2);
                        xb1[2*i+1] = __ldg(xg2 + cid * 2 + 1);
                    }
                }
            }

            // store refill batch 2
            if (do2) {
                #pragma unroll
                for (int i = 0; i < 4; ++i) {
                    int cid = et + (i + 4) * 256;
                    int w = cid >> 5, cc = cid & 31;
                    sts128(xbdst + (uint32_t)(w * 512 + ((cc ^ (w & 7)) << 4)),
                           packbf(xb1[2*i].x, xb1[2*i].y), packbf(xb1[2*i].z, xb1[2*i].w),
                           packbf(xb1[2*i+1].x, xb1[2*i+1].y), packbf(xb1[2*i+1].z, xb1[2*i+1].w));
                }
            }

            bar_sync(3, 256);                // epi warps done reading ybuf
            #pragma unroll
            for (int j = 0; j < 4; ++j)
                sts64f(sb + Y_OFF + (uint32_t)(ewid * 1024 + (2 * l + 64 * j) * 4),
                       p[2*j], p[2*j+1]);
            bar_sync(3, 256);                // partials visible
            {
                float o = 0.f;
                #pragma unroll
                for (int we = 0; we < 8; ++we)
                    o += smf[Y_OFF / 4 + we * 256 + et];
                out[(size_t)s * 256 + et] = o;
            }
            membar_cta();
            bar_arrive(2, 512);              // ybuf free + xb refilled
        }
    }
}

extern "C" void kernel_launch(void* const* d_in, const int* in_sizes, int n_in,
                              void* d_out, int out_size)
{
    const float* x   = (const float*)d_in[0];
    const float* Wm  = (const float*)d_in[1];
    const float* b   = (const float*)d_in[2];
    const float* ctx = (const float*)d_in[3];
    float* out = (float*)d_out;

    int dev = 0, sms = 148;
    cudaGetDevice(&dev);
    cudaDeviceGetAttribute(&sms, cudaDevAttrMultiProcessorCount, dev);

    cudaFuncSetAttribute(attend_ws, cudaFuncAttributeMaxDynamicSharedMemorySize, SMEM_BYTES);

    conv_w<<<64, 256>>>(Wm);
    attend_ws<<<sms, 512, SMEM_BYTES>>>(x, b, ctx, out);
}